// round 12
// baseline (speedup 1.0000x reference)
#include <cuda_runtime.h>
#include <math.h>

#define KW   9
#define PAD  4
#define BX   64            // threads in x == tile width (PXT=1)
#define BY   4             // threads in y == tile height
#define TW   64
#define TH   4
#define SXU  (TW + 2*PAD)  // 72 used smem cols
#define SXP  76            // padded smem row stride (76*4B = 304B, 16B-aligned)
#define SY   (TH + 2*PAD)  // 12 smem rows
#define HH   256
#define WW   256
#define CC   3
#define NV4  18            // float4 cols covering SXU
#define NPRE (CC*4*TH*NV4) // 864 pre-add float4 ops

#define INV_DIAG (1.0f / 362.03867196751236f)
#define SIGMA_MIN 0.5f
#define SIGMA_RANGE 9.5f
#define PI_F 3.14159265358979323846f

// rows 0..4 of the symmetric 9x9 q-index map (row oy == row 8-oy)
__device__ constexpr int QIDX5[5][9] = {
    {14,13,12,10, 9,10,12,13,14},
    {13,11, 8, 7, 6, 7, 8,11,13},
    {12, 8, 5, 4, 3, 4, 5, 8,12},
    {10, 7, 4, 2, 1, 2, 4, 7,10},
    { 9, 6, 3, 1, 0, 1, 3, 6, 9},
};

__device__ __forceinline__ int reflect_idx(int v) {
    v = (v < 0) ? -v : v;
    return (v >= HH) ? (2 * HH - 2 - v) : v;   // H == W == 256
}

__device__ __forceinline__ void make_weights(float ddx, float ddy, float* w)
{
    const float d2   = ddx * ddx + ddy * ddy;
    const float dist = sqrtf(d2);
    const float s    = SIGMA_MIN + SIGMA_RANGE * (dist * INV_DIAG);
    const float s2   = s * s;
    const float a    = 0.5f / s2;
    const float common = -dist * sqrtf(s) * __fdividef(1.0f, PI_F * s2 * s2);

    const float E   = __expf(-a);
    const float E2  = E  * E,  E4  = E2  * E2, E5  = E4  * E;
    const float E8  = E4 * E4, E9  = E8  * E,  E10 = E8  * E2;
    const float E13 = E8 * E5, E16 = E8  * E8, E17 = E16 * E;
    const float E18 = E16* E2, E20 = E16 * E4, E25 = E16 * E9;
    const float E32 = E16 * E16;

    w[0]  = common;
    w[1]  = common * fmaf( -1.0f, a, 1.0f) * E;
    w[2]  = common * fmaf( -2.0f, a, 1.0f) * E2;
    w[3]  = common * fmaf( -4.0f, a, 1.0f) * E4;
    w[4]  = common * fmaf( -5.0f, a, 1.0f) * E5;
    w[5]  = common * fmaf( -8.0f, a, 1.0f) * E8;
    w[6]  = common * fmaf( -9.0f, a, 1.0f) * E9;
    w[7]  = common * fmaf(-10.0f, a, 1.0f) * E10;
    w[8]  = common * fmaf(-13.0f, a, 1.0f) * E13;
    w[9]  = common * fmaf(-16.0f, a, 1.0f) * E16;
    w[10] = common * fmaf(-17.0f, a, 1.0f) * E17;
    w[11] = common * fmaf(-18.0f, a, 1.0f) * E18;
    w[12] = common * fmaf(-20.0f, a, 1.0f) * E20;
    w[13] = common * fmaf(-25.0f, a, 1.0f) * E25;
    w[14] = common * fmaf(-32.0f, a, 1.0f) * E32;
}

// 7 CTAs/SM -> 1024 CTAs fit in ONE wave (7*148 = 1036); regs forced <= 36
__global__ __launch_bounds__(BX * BY, 7)
void adaptive_log_conv(const float* __restrict__ x,
                       const float* __restrict__ foa,
                       float* __restrict__ out)
{
    __shared__ __align__(16) float sm[CC][SY][SXP];    // 10.9 KB
    __shared__ __align__(16) float pr[CC][4][TH][SXP]; // 14.6 KB

    const int b   = blockIdx.z;
    const int bx0 = blockIdx.x * TW;
    const int by0 = blockIdx.y * TH;
    const int lx  = threadIdx.x;      // 0..63
    const int ly  = threadIdx.y;      // 0..3
    const int tid = ly * BX + lx;

    const float* xb = x + (size_t)b * CC * HH * WW;

    // ---- tile load: 256 threads, rows {ly, ly+4, ly+8}, cols lx (+ lx+64 for lx<8) ----
    const int gy0 = reflect_idx(by0 + ly     - PAD);
    const int gy1 = reflect_idx(by0 + ly + 4 - PAD);
    const int gy2 = reflect_idx(by0 + ly + 8 - PAD);
    const int gxa = reflect_idx(bx0 + lx      - PAD);
    const int gxb = reflect_idx(bx0 + lx + 64 - PAD);
    const bool hasb = (lx < SXU - 64);     // lx < 8

    #pragma unroll
    for (int c = 0; c < CC; c++) {
        const float* xc = xb + c * (HH * WW);
        const float* r0 = xc + gy0 * WW;
        const float* r1 = xc + gy1 * WW;
        const float* r2 = xc + gy2 * WW;
        sm[c][ly    ][lx] = r0[gxa];
        sm[c][ly + 4][lx] = r1[gxa];
        sm[c][ly + 8][lx] = r2[gxa];
        if (hasb) {
            sm[c][ly    ][lx + 64] = r0[gxb];
            sm[c][ly + 4][lx + 64] = r1[gxb];
            sm[c][ly + 8][lx + 64] = r2[gxb];
        }
    }

    // ---- weight generation: ONE pixel per thread (overlaps in-flight loads) ----
    const int px = bx0 + lx;
    const int py = by0 + ly;
    const float fx  = foa[b * 2 + 0];
    const float fy  = foa[b * 2 + 1];

    float w[15];
    make_weights((float)px - fx, (float)py - fy, w);

    __syncthreads();

    // ---- paired-row pre-add distributed over all 256 threads (864 float4 ops) ----
    #pragma unroll
    for (int k = 0; k < 4; k++) {
        const int i = tid + k * 256;
        if (i < NPRE) {                       // k=3: tid<96 -> warps 0-2 (warp-uniform)
            const int vc  = i % NV4;          // const-div: mulhi+shift
            const int s   = i / NV4;          // 0..47
            const int row = s & 3;
            const int u   = s >> 2;           // 0..11
            const int a   = u & 3;
            const int c   = u >> 2;
            const float4 p = *(const float4*)&sm[c][row + a    ][4 * vc];
            const float4 q = *(const float4*)&sm[c][row + 8 - a][4 * vc];
            float4 r;
            r.x = p.x + q.x; r.y = p.y + q.y;
            r.z = p.z + q.z; r.w = p.w + q.w;
            *(float4*)&pr[c][a][row][4 * vc] = r;
        }
    }
    __syncthreads();

    // ---- convolution: 5 effective rows x 3 channels, 9 taps each ----
    float acc[CC];
    #pragma unroll
    for (int c = 0; c < CC; c++) acc[c] = 0.0f;

    #pragma unroll
    for (int c = 0; c < CC; c++) {
        #pragma unroll
        for (int a = 0; a < 5; a++) {
            const float* row = (a < 4) ? &pr[c][a][ly][lx]
                                       : &sm[c][ly + 4][lx];
            #pragma unroll
            for (int ox = 0; ox < KW; ox++) {
                acc[c] = fmaf(row[ox], w[QIDX5[a][ox]], acc[c]);
            }
        }
    }

    float* ob = out + (size_t)b * CC * HH * WW;
    #pragma unroll
    for (int c = 0; c < CC; c++)
        ob[(c * HH + py) * WW + px] = acc[c];
}

extern "C" void kernel_launch(void* const* d_in, const int* in_sizes, int n_in,
                              void* d_out, int out_size)
{
    const float* x   = (const float*)d_in[0];
    const float* foa = (const float*)d_in[1];
    float* out = (float*)d_out;

    dim3 block(BX, BY, 1);
    dim3 grid(WW / TW, HH / TH, 4);   // 1024 CTAs x 256 threads, single wave at occ 7
    adaptive_log_conv<<<grid, block>>>(x, foa, out);
}

// round 13
// speedup vs baseline: 1.0150x; 1.0150x over previous
#include <cuda_runtime.h>
#include <math.h>

#define KW   9
#define PAD  4
#define BX   64            // threads in x == tile width (1 px/thread)
#define BY   4
#define TW   64
#define TH   4
#define SXU  (TW + 2*PAD)  // 72 used smem cols
#define SXP  76            // padded row stride (304B, 16B-aligned)
#define HH   256
#define WW   256
#define CC   3

#define INV_DIAG (1.0f / 362.03867196751236f)
#define SIGMA_MIN 0.5f
#define SIGMA_RANGE 9.5f
#define PI_F 3.14159265358979323846f

// rows 0..4 of the symmetric 9x9 q-index map (row oy == row 8-oy)
__device__ constexpr int QIDX5[5][9] = {
    {14,13,12,10, 9,10,12,13,14},
    {13,11, 8, 7, 6, 7, 8,11,13},
    {12, 8, 5, 4, 3, 4, 5, 8,12},
    {10, 7, 4, 2, 1, 2, 4, 7,10},
    { 9, 6, 3, 1, 0, 1, 3, 6, 9},
};

__device__ __forceinline__ int reflect_idx(int v) {
    v = (v < 0) ? -v : v;
    return (v >= HH) ? (2 * HH - 2 - v) : v;   // H == W == 256
}

__device__ __forceinline__ void make_weights(float ddx, float ddy, float* w)
{
    const float d2   = ddx * ddx + ddy * ddy;
    const float dist = sqrtf(d2);
    const float s    = SIGMA_MIN + SIGMA_RANGE * (dist * INV_DIAG);
    const float s2   = s * s;
    const float a    = 0.5f / s2;
    const float common = -dist * sqrtf(s) * __fdividef(1.0f, PI_F * s2 * s2);

    const float E   = __expf(-a);
    const float E2  = E  * E,  E4  = E2  * E2, E5  = E4  * E;
    const float E8  = E4 * E4, E9  = E8  * E,  E10 = E8  * E2;
    const float E13 = E8 * E5, E16 = E8  * E8, E17 = E16 * E;
    const float E18 = E16* E2, E20 = E16 * E4, E25 = E16 * E9;
    const float E32 = E16 * E16;

    w[0]  = common;
    w[1]  = common * fmaf( -1.0f, a, 1.0f) * E;
    w[2]  = common * fmaf( -2.0f, a, 1.0f) * E2;
    w[3]  = common * fmaf( -4.0f, a, 1.0f) * E4;
    w[4]  = common * fmaf( -5.0f, a, 1.0f) * E5;
    w[5]  = common * fmaf( -8.0f, a, 1.0f) * E8;
    w[6]  = common * fmaf( -9.0f, a, 1.0f) * E9;
    w[7]  = common * fmaf(-10.0f, a, 1.0f) * E10;
    w[8]  = common * fmaf(-13.0f, a, 1.0f) * E13;
    w[9]  = common * fmaf(-16.0f, a, 1.0f) * E16;
    w[10] = common * fmaf(-17.0f, a, 1.0f) * E17;
    w[11] = common * fmaf(-18.0f, a, 1.0f) * E18;
    w[12] = common * fmaf(-20.0f, a, 1.0f) * E20;
    w[13] = common * fmaf(-25.0f, a, 1.0f) * E25;
    w[14] = common * fmaf(-32.0f, a, 1.0f) * E32;
}

// 7 CTAs/SM -> single wave (7*148 = 1036 >= 1024)
__global__ __launch_bounds__(BX * BY, 7)
void adaptive_log_conv(const float* __restrict__ x,
                       const float* __restrict__ foa,
                       float* __restrict__ out)
{
    // paired-row sums built DIRECTLY from gmem; no raw tile in smem
    __shared__ __align__(16) float pr[CC][4][TH][SXP];  // 14.6 KB
    __shared__ __align__(16) float mid[CC][TH][SXP];    //  3.6 KB

    const int b   = blockIdx.z;
    const int bx0 = blockIdx.x * TW;
    const int by0 = blockIdx.y * TH;
    const int lx  = threadIdx.x;      // 0..63
    const int ly  = threadIdx.y;      // 0..3
    const int tid = ly * BX + lx;

    const float* xb = x + (size_t)b * CC * HH * WW;

    // ---- A: pr central — 768 float4 units (3/thread), all-pow2 decode ----
    // smem col s <-> global x = bx0 + s - PAD; central float4 v -> smem col 4+4v
    #pragma unroll
    for (int k = 0; k < 3; k++) {
        const int i   = tid + k * 256;
        const int v   = i & 15;           // float4 column 0..15
        const int t   = i >> 4;           // 0..47
        const int row = t & 3;
        const int u   = t >> 2;           // 0..11
        const int a   = u & 3;
        const int c   = u >> 2;
        const int gy1 = reflect_idx(by0 + row + a     - PAD);
        const int gy2 = reflect_idx(by0 + row + 8 - a - PAD);
        const float* base = xb + c * (HH * WW);
        const float4 p = *(const float4*)(base + gy1 * WW + bx0 + 4 * v);
        const float4 q = *(const float4*)(base + gy2 * WW + bx0 + 4 * v);
        float4 r;
        r.x = p.x + q.x; r.y = p.y + q.y;
        r.z = p.z + q.z; r.w = p.w + q.w;
        *(float4*)&pr[c][a][row][4 + 4 * v] = r;
    }

    // ---- B: pr halo — 384 scalars (k=1 covers tid<128: warps 0-3, uniform) ----
    #pragma unroll
    for (int k = 0; k < 2; k++) {
        const int j = tid + k * 256;
        if (j < 384) {
            const int h   = j & 7;
            const int t   = j >> 3;       // 0..47
            const int row = t & 3;
            const int u   = t >> 2;
            const int a   = u & 3;
            const int c   = u >> 2;
            const int s   = (h < 4) ? h : h + 64;        // smem col 0..3 / 68..71
            const int gx  = reflect_idx(bx0 + s - PAD);
            const int gy1 = reflect_idx(by0 + row + a     - PAD);
            const int gy2 = reflect_idx(by0 + row + 8 - a - PAD);
            const float* base = xb + c * (HH * WW);
            pr[c][a][row][s] = base[gy1 * WW + gx] + base[gy2 * WW + gx];
        }
    }

    // ---- C: middle rows central — 192 float4 units (tid<192: warps 0-5) ----
    if (tid < 192) {
        const int v   = tid & 15;
        const int t   = tid >> 4;         // 0..11
        const int row = t & 3;
        const int c   = t >> 2;
        const float* base = xb + c * (HH * WW);
        const float4 p = *(const float4*)(base + (by0 + row) * WW + bx0 + 4 * v);
        *(float4*)&mid[c][row][4 + 4 * v] = p;   // middle row always in-bounds in y
    }

    // ---- D: middle rows halo — 96 scalars (tid<96: warps 0-2) ----
    if (tid < 96) {
        const int h   = tid & 7;
        const int t   = tid >> 3;         // 0..11
        const int row = t & 3;
        const int c   = t >> 2;
        const int s   = (h < 4) ? h : h + 64;
        const int gx  = reflect_idx(bx0 + s - PAD);
        const float* base = xb + c * (HH * WW);
        mid[c][row][s] = base[(by0 + row) * WW + gx];
    }

    // ---- weight generation overlaps all in-flight LDGs ----
    const int px = bx0 + lx;
    const int py = by0 + ly;
    const float fx = foa[b * 2 + 0];
    const float fy = foa[b * 2 + 1];

    float w[15];
    make_weights((float)px - fx, (float)py - fy, w);

    __syncthreads();   // the ONLY barrier

    // ---- convolution: 5 effective rows x 3 channels x 9 taps ----
    float acc[CC];
    #pragma unroll
    for (int c = 0; c < CC; c++) acc[c] = 0.0f;

    #pragma unroll
    for (int c = 0; c < CC; c++) {
        #pragma unroll
        for (int a = 0; a < 5; a++) {
            const float* row = (a < 4) ? &pr[c][a][ly][lx]
                                       : &mid[c][ly][lx];
            #pragma unroll
            for (int ox = 0; ox < KW; ox++) {
                acc[c] = fmaf(row[ox], w[QIDX5[a][ox]], acc[c]);
            }
        }
    }

    float* ob = out + (size_t)b * CC * HH * WW;
    #pragma unroll
    for (int c = 0; c < CC; c++)
        ob[(c * HH + py) * WW + px] = acc[c];
}

extern "C" void kernel_launch(void* const* d_in, const int* in_sizes, int n_in,
                              void* d_out, int out_size)
{
    const float* x   = (const float*)d_in[0];
    const float* foa = (const float*)d_in[1];
    float* out = (float*)d_out;

    dim3 block(BX, BY, 1);
    dim3 grid(WW / TW, HH / TH, 4);   // 1024 CTAs, single wave at occ 7
    adaptive_log_conv<<<grid, block>>>(x, foa, out);
}

// round 14
// speedup vs baseline: 1.2113x; 1.1935x over previous
#include <cuda_runtime.h>
#include <math.h>

#define KW   9
#define PAD  4
#define TXL  32            // threads x
#define TYL  4             // threads y
#define PXT  2             // pixels per thread
#define TW   64            // tile width
#define TH   4             // tile height
#define SXU  (TW + 2*PAD)  // 72 used smem cols
#define SXP  76            // padded row stride (304B)
#define HH   256
#define WW   256
#define CC   3

#define INV_DIAG (1.0f / 362.03867196751236f)
#define SIGMA_MIN 0.5f
#define SIGMA_RANGE 9.5f
#define PI_F 3.14159265358979323846f

// rows 0..4 of the symmetric 9x9 q-index map (row oy == row 8-oy)
__device__ constexpr int QIDX5[5][9] = {
    {14,13,12,10, 9,10,12,13,14},
    {13,11, 8, 7, 6, 7, 8,11,13},
    {12, 8, 5, 4, 3, 4, 5, 8,12},
    {10, 7, 4, 2, 1, 2, 4, 7,10},
    { 9, 6, 3, 1, 0, 1, 3, 6, 9},
};

__device__ __forceinline__ int reflect_idx(int v) {
    v = (v < 0) ? -v : v;
    return (v >= HH) ? (2 * HH - 2 - v) : v;   // H == W == 256
}

__device__ __forceinline__ void make_weights(float ddx, float ddy, float* w)
{
    const float d2   = ddx * ddx + ddy * ddy;
    const float dist = sqrtf(d2);
    const float s    = SIGMA_MIN + SIGMA_RANGE * (dist * INV_DIAG);
    const float s2   = s * s;
    const float a    = 0.5f / s2;
    const float common = -dist * sqrtf(s) * __fdividef(1.0f, PI_F * s2 * s2);

    const float E   = __expf(-a);
    const float E2  = E  * E,  E4  = E2  * E2, E5  = E4  * E;
    const float E8  = E4 * E4, E9  = E8  * E,  E10 = E8  * E2;
    const float E13 = E8 * E5, E16 = E8  * E8, E17 = E16 * E;
    const float E18 = E16* E2, E20 = E16 * E4, E25 = E16 * E9;
    const float E32 = E16 * E16;

    w[0]  = common;
    w[1]  = common * fmaf( -1.0f, a, 1.0f) * E;
    w[2]  = common * fmaf( -2.0f, a, 1.0f) * E2;
    w[3]  = common * fmaf( -4.0f, a, 1.0f) * E4;
    w[4]  = common * fmaf( -5.0f, a, 1.0f) * E5;
    w[5]  = common * fmaf( -8.0f, a, 1.0f) * E8;
    w[6]  = common * fmaf( -9.0f, a, 1.0f) * E9;
    w[7]  = common * fmaf(-10.0f, a, 1.0f) * E10;
    w[8]  = common * fmaf(-13.0f, a, 1.0f) * E13;
    w[9]  = common * fmaf(-16.0f, a, 1.0f) * E16;
    w[10] = common * fmaf(-17.0f, a, 1.0f) * E17;
    w[11] = common * fmaf(-18.0f, a, 1.0f) * E18;
    w[12] = common * fmaf(-20.0f, a, 1.0f) * E20;
    w[13] = common * fmaf(-25.0f, a, 1.0f) * E25;
    w[14] = common * fmaf(-32.0f, a, 1.0f) * E32;
}

// 128 threads/CTA, occ 8 -> 1024 CTAs in one wave (8*148 = 1184)
__global__ __launch_bounds__(TXL * TYL, 8)
void adaptive_log_conv(const float* __restrict__ x,
                       const float* __restrict__ foa,
                       float* __restrict__ out)
{
    // paired-row sums built DIRECTLY from gmem; no raw tile round-trip
    __shared__ __align__(16) float pr[CC][4][TH][SXP];  // 14.6 KB
    __shared__ __align__(16) float mid[CC][TH][SXP];    //  3.6 KB

    const int b   = blockIdx.z;
    const int bx0 = blockIdx.x * TW;
    const int by0 = blockIdx.y * TH;
    const int lx  = threadIdx.x;      // 0..31
    const int ly  = threadIdx.y;      // 0..3
    const int tid = ly * TXL + lx;    // 0..127

    const float* xb = x + (size_t)b * CC * HH * WW;

    // ---- pr central: 768 float4 units, exactly 6 per thread, pow2 decode ----
    #pragma unroll
    for (int k = 0; k < 6; k++) {
        const int i   = tid + k * 128;
        const int v   = i & 15;           // float4 col 0..15
        const int t   = i >> 4;           // 0..47
        const int row = t & 3;
        const int u   = t >> 2;           // 0..11
        const int a   = u & 3;
        const int c   = u >> 2;
        const int gy1 = reflect_idx(by0 + row + a     - PAD);
        const int gy2 = reflect_idx(by0 + row + 8 - a - PAD);
        const float* base = xb + c * (HH * WW);
        const float4 p = *(const float4*)(base + gy1 * WW + bx0 + 4 * v);
        const float4 q = *(const float4*)(base + gy2 * WW + bx0 + 4 * v);
        float4 r;
        r.x = p.x + q.x; r.y = p.y + q.y;
        r.z = p.z + q.z; r.w = p.w + q.w;
        *(float4*)&pr[c][a][row][4 + 4 * v] = r;
    }

    // ---- pr halo: 384 scalars, exactly 3 per thread ----
    #pragma unroll
    for (int k = 0; k < 3; k++) {
        const int j   = tid + k * 128;
        const int h   = j & 7;
        const int t   = j >> 3;           // 0..47
        const int row = t & 3;
        const int u   = t >> 2;
        const int a   = u & 3;
        const int c   = u >> 2;
        const int s   = (h < 4) ? h : h + 64;   // smem col 0..3 / 68..71
        const int gx  = reflect_idx(bx0 + s - PAD);
        const int gy1 = reflect_idx(by0 + row + a     - PAD);
        const int gy2 = reflect_idx(by0 + row + 8 - a - PAD);
        const float* base = xb + c * (HH * WW);
        pr[c][a][row][s] = base[gy1 * WW + gx] + base[gy2 * WW + gx];
    }

    // ---- mid central: 192 float4 units (k=1 tail: tid<64 = warps 0-1) ----
    #pragma unroll
    for (int k = 0; k < 2; k++) {
        const int i = tid + k * 128;
        if (i < 192) {
            const int v   = i & 15;
            const int t   = i >> 4;       // 0..11
            const int row = t & 3;
            const int c   = t >> 2;
            const float* base = xb + c * (HH * WW);
            const float4 p = *(const float4*)(base + (by0 + row) * WW + bx0 + 4 * v);
            *(float4*)&mid[c][row][4 + 4 * v] = p;   // middle rows always in-bounds in y
        }
    }

    // ---- mid halo: 96 scalars (tid<96 = warps 0-2) ----
    if (tid < 96) {
        const int h   = tid & 7;
        const int t   = tid >> 3;         // 0..11
        const int row = t & 3;
        const int c   = t >> 2;
        const int s   = (h < 4) ? h : h + 64;
        const int gx  = reflect_idx(bx0 + s - PAD);
        const float* base = xb + c * (HH * WW);
        mid[c][row][s] = base[(by0 + row) * WW + gx];
    }

    // ---- weight generation for BOTH pixels (overlaps in-flight LDGs) ----
    const int px0 = bx0 + PXT * lx;
    const int py  = by0 + ly;
    const float fx  = foa[b * 2 + 0];
    const float fy  = foa[b * 2 + 1];
    const float ddy = (float)py - fy;

    float w0[15], w1[15];
    make_weights((float)(px0    ) - fx, ddy, w0);
    make_weights((float)(px0 + 1) - fx, ddy, w1);

    __syncthreads();   // the ONLY barrier

    // ---- convolution: 5 effective rows x 3 channels, 2 pixels/thread ----
    float acc[CC][PXT];
    #pragma unroll
    for (int c = 0; c < CC; c++) { acc[c][0] = 0.0f; acc[c][1] = 0.0f; }

    #pragma unroll
    for (int c = 0; c < CC; c++) {
        #pragma unroll
        for (int a = 0; a < 5; a++) {
            const float* row = (a < 4) ? &pr[c][a][ly][PXT * lx]
                                       : &mid[c][ly][PXT * lx];
            const float2 p0 = *(const float2*)(row + 0);
            const float2 p1 = *(const float2*)(row + 2);
            const float2 p2 = *(const float2*)(row + 4);
            const float2 p3 = *(const float2*)(row + 6);
            const float2 p4 = *(const float2*)(row + 8);
            float t[10];
            t[0] = p0.x; t[1] = p0.y; t[2] = p1.x; t[3] = p1.y;
            t[4] = p2.x; t[5] = p2.y; t[6] = p3.x; t[7] = p3.y;
            t[8] = p4.x; t[9] = p4.y;
            #pragma unroll
            for (int ox = 0; ox < KW; ox++) {
                const int q = QIDX5[a][ox];
                acc[c][0] = fmaf(t[ox    ], w0[q], acc[c][0]);
                acc[c][1] = fmaf(t[ox + 1], w1[q], acc[c][1]);
            }
        }
    }

    float* ob = out + (size_t)b * CC * HH * WW;
    #pragma unroll
    for (int c = 0; c < CC; c++) {
        float2 r;
        r.x = acc[c][0]; r.y = acc[c][1];
        *(float2*)&ob[(c * HH + py) * WW + px0] = r;
    }
}

extern "C" void kernel_launch(void* const* d_in, const int* in_sizes, int n_in,
                              void* d_out, int out_size)
{
    const float* x   = (const float*)d_in[0];
    const float* foa = (const float*)d_in[1];
    float* out = (float*)d_out;

    dim3 block(TXL, TYL, 1);
    dim3 grid(WW / TW, HH / TH, 4);   // 1024 CTAs x 128 threads, single wave at occ 8
    adaptive_log_conv<<<grid, block>>>(x, foa, out);
}

// round 15
// speedup vs baseline: 1.2149x; 1.0030x over previous
#include <cuda_runtime.h>
#include <math.h>

#define KW   9
#define PAD  4
#define TXL  32
#define TYL  4
#define PXT  2
#define TW   64
#define TH   4
#define SXU  (TW + 2*PAD)  // 72
#define SXP  76            // padded row stride
#define HH   256
#define WW   256
#define CC   3

#define INV_DIAG (1.0f / 362.03867196751236f)
#define SIGMA_MIN 0.5f
#define SIGMA_RANGE 9.5f
#define PI_F 3.14159265358979323846f

// rows 0..4 of the symmetric 9x9 q-index map (row oy == row 8-oy)
__device__ constexpr int QIDX5[5][9] = {
    {14,13,12,10, 9,10,12,13,14},
    {13,11, 8, 7, 6, 7, 8,11,13},
    {12, 8, 5, 4, 3, 4, 5, 8,12},
    {10, 7, 4, 2, 1, 2, 4, 7,10},
    { 9, 6, 3, 1, 0, 1, 3, 6, 9},
};

__device__ __forceinline__ int reflect_idx(int v) {
    v = (v < 0) ? -v : v;
    return (v >= HH) ? (2 * HH - 2 - v) : v;   // H == W == 256
}

// Unnormalized: u[q] = (1 - q*a) * E^q. Returns 'common' (applied once per acc).
__device__ __forceinline__ float make_weights_u(float ddx, float ddy, float* u)
{
    const float d2   = ddx * ddx + ddy * ddy;
    const float dist = sqrtf(d2);
    const float s    = SIGMA_MIN + SIGMA_RANGE * (dist * INV_DIAG);
    const float s2   = s * s;
    const float a    = 0.5f / s2;
    const float common = -dist * sqrtf(s) * __fdividef(1.0f, PI_F * s2 * s2);

    const float E   = __expf(-a);
    const float E2  = E  * E,  E4  = E2  * E2, E5  = E4  * E;
    const float E8  = E4 * E4, E9  = E8  * E,  E10 = E8  * E2;
    const float E13 = E8 * E5, E16 = E8  * E8, E17 = E16 * E;
    const float E18 = E16* E2, E20 = E16 * E4, E25 = E16 * E9;
    const float E32 = E16 * E16;

    u[0]  = 1.0f;
    u[1]  = fmaf( -1.0f, a, 1.0f) * E;
    u[2]  = fmaf( -2.0f, a, 1.0f) * E2;
    u[3]  = fmaf( -4.0f, a, 1.0f) * E4;
    u[4]  = fmaf( -5.0f, a, 1.0f) * E5;
    u[5]  = fmaf( -8.0f, a, 1.0f) * E8;
    u[6]  = fmaf( -9.0f, a, 1.0f) * E9;
    u[7]  = fmaf(-10.0f, a, 1.0f) * E10;
    u[8]  = fmaf(-13.0f, a, 1.0f) * E13;
    u[9]  = fmaf(-16.0f, a, 1.0f) * E16;
    u[10] = fmaf(-17.0f, a, 1.0f) * E17;
    u[11] = fmaf(-18.0f, a, 1.0f) * E18;
    u[12] = fmaf(-20.0f, a, 1.0f) * E20;
    u[13] = fmaf(-25.0f, a, 1.0f) * E25;
    u[14] = fmaf(-32.0f, a, 1.0f) * E32;
    return common;
}

// 128 threads/CTA, occ 8 -> 1024 CTAs in one wave (8*148 = 1184)
__global__ __launch_bounds__(TXL * TYL, 8)
void adaptive_log_conv(const float* __restrict__ x,
                       const float* __restrict__ foa,
                       float* __restrict__ out)
{
    __shared__ __align__(16) float pr[CC][4][TH][SXP];  // 14.6 KB paired-row sums
    __shared__ __align__(16) float mid[CC][TH][SXP];    //  3.6 KB middle rows

    const int b   = blockIdx.z;
    const int bx0 = blockIdx.x * TW;
    const int by0 = blockIdx.y * TH;
    const int lx  = threadIdx.x;      // 0..31
    const int ly  = threadIdx.y;      // 0..3
    const int tid = ly * TXL + lx;    // 0..127

    const float* xb = x + (size_t)b * CC * HH * WW;

    // ======== pr central: all decode per-thread constant ========
    // 768 float4 units = 128 threads x (2 'a' values x 3 channels)
    {
        const int v   = tid & 15;
        const int row = (tid >> 4) & 3;
        const int a0  = tid >> 6;             // 0 or 1
        const int a1  = a0 + 2;               // 2 or 3
        const int ga0 = reflect_idx(by0 + row + a0 - PAD);
        const int gb0 = reflect_idx(by0 + row + 4 - a0);   // 8-a0 mirrored row
        const int ga1 = reflect_idx(by0 + row + a1 - PAD);
        const int gb1 = reflect_idx(by0 + row + 4 - a1);
        const int col = bx0 + 4 * v;
        const int sc  = 4 + 4 * v;
        #pragma unroll
        for (int c = 0; c < CC; c++) {
            const float* base = xb + c * (HH * WW);
            float4 p = *(const float4*)(base + ga0 * WW + col);
            float4 q = *(const float4*)(base + gb0 * WW + col);
            float4 r;
            r.x = p.x + q.x; r.y = p.y + q.y; r.z = p.z + q.z; r.w = p.w + q.w;
            *(float4*)&pr[c][a0][row][sc] = r;

            p = *(const float4*)(base + ga1 * WW + col);
            q = *(const float4*)(base + gb1 * WW + col);
            r.x = p.x + q.x; r.y = p.y + q.y; r.z = p.z + q.z; r.w = p.w + q.w;
            *(float4*)&pr[c][a1][row][sc] = r;
        }
    }

    // ======== pr halo: h,row,a constant; c = loop index ========
    // 384 scalars = 128 threads x 3 channels
    {
        const int h    = tid & 7;
        const int rowh = (tid >> 3) & 3;
        const int ah   = (tid >> 5) & 3;
        const int s    = (h < 4) ? h : h + 64;
        const int gx   = reflect_idx(bx0 + s - PAD);
        const int gy1  = reflect_idx(by0 + rowh + ah - PAD);
        const int gy2  = reflect_idx(by0 + rowh + 4 - ah);
        #pragma unroll
        for (int c = 0; c < CC; c++) {
            const float* base = xb + c * (HH * WW);
            pr[c][ah][rowh][s] = base[gy1 * WW + gx] + base[gy2 * WW + gx];
        }
    }

    // ======== mid central: 192 float4 units ========
    {
        const int v   = tid & 15;
        const int row = (tid >> 4) & 3;
        const int c0  = tid >> 6;             // 0 or 1
        const int col = bx0 + 4 * v;
        const int gy  = (by0 + row) * WW;     // middle rows always in-bounds in y
        const float4 p = *(const float4*)(xb + c0 * (HH * WW) + gy + col);
        *(float4*)&mid[c0][row][4 + 4 * v] = p;
        if (tid < 64) {                        // c = 2 (warps 0-1, uniform)
            const float4 p2 = *(const float4*)(xb + 2 * (HH * WW) + gy + col);
            *(float4*)&mid[2][row][4 + 4 * v] = p2;
        }
    }

    // ======== mid halo: 96 scalars (warps 0-2) ========
    if (tid < 96) {
        const int h   = tid & 7;
        const int row = (tid >> 3) & 3;
        const int c   = tid >> 5;
        const int s   = (h < 4) ? h : h + 64;
        const int gx  = reflect_idx(bx0 + s - PAD);
        mid[c][row][s] = xb[c * (HH * WW) + (by0 + row) * WW + gx];
    }

    // ======== weight generation (overlaps in-flight LDGs) ========
    const int px0 = bx0 + PXT * lx;
    const int py  = by0 + ly;
    const float fx  = foa[b * 2 + 0];
    const float fy  = foa[b * 2 + 1];
    const float ddy = (float)py - fy;

    float w0[15], w1[15];
    const float common0 = make_weights_u((float)(px0    ) - fx, ddy, w0);
    const float common1 = make_weights_u((float)(px0 + 1) - fx, ddy, w1);

    __syncthreads();   // the ONLY barrier

    // ======== convolution: 5 effective rows x 3 channels, 2 px/thread ========
    float acc[CC][PXT];
    #pragma unroll
    for (int c = 0; c < CC; c++) { acc[c][0] = 0.0f; acc[c][1] = 0.0f; }

    #pragma unroll
    for (int c = 0; c < CC; c++) {
        #pragma unroll
        for (int a = 0; a < 5; a++) {
            const float* row = (a < 4) ? &pr[c][a][ly][PXT * lx]
                                       : &mid[c][ly][PXT * lx];
            const float2 p0 = *(const float2*)(row + 0);
            const float2 p1 = *(const float2*)(row + 2);
            const float2 p2 = *(const float2*)(row + 4);
            const float2 p3 = *(const float2*)(row + 6);
            const float2 p4 = *(const float2*)(row + 8);
            float t[10];
            t[0] = p0.x; t[1] = p0.y; t[2] = p1.x; t[3] = p1.y;
            t[4] = p2.x; t[5] = p2.y; t[6] = p3.x; t[7] = p3.y;
            t[8] = p4.x; t[9] = p4.y;
            #pragma unroll
            for (int ox = 0; ox < KW; ox++) {
                const int q = QIDX5[a][ox];
                acc[c][0] = fmaf(t[ox    ], w0[q], acc[c][0]);
                acc[c][1] = fmaf(t[ox + 1], w1[q], acc[c][1]);
            }
        }
    }

    float* ob = out + (size_t)b * CC * HH * WW;
    #pragma unroll
    for (int c = 0; c < CC; c++) {
        float2 r;
        r.x = acc[c][0] * common0;
        r.y = acc[c][1] * common1;
        *(float2*)&ob[(c * HH + py) * WW + px0] = r;
    }
}

extern "C" void kernel_launch(void* const* d_in, const int* in_sizes, int n_in,
                              void* d_out, int out_size)
{
    const float* x   = (const float*)d_in[0];
    const float* foa = (const float*)d_in[1];
    float* out = (float*)d_out;

    dim3 block(TXL, TYL, 1);
    dim3 grid(WW / TW, HH / TH, 4);   // 1024 CTAs x 128 threads, single wave
    adaptive_log_conv<<<grid, block>>>(x, foa, out);
}